// round 13
// baseline (speedup 1.0000x reference)
#include <cuda_runtime.h>

// inputs (128, 64, 64, 32) fp32 => B=128, N=64 rows/batch, D=2048.
// loss = mean_b( || sum_n att[b,n,:] ||^2 - sum_n <att_n,att_n> ),
// att = x / max(||x||,1e-12) row-wise.
//
// Single-L2-pass design, occupancy-first:
//  - warp fully owns rows (32 lanes x 16 f4 = full row width)
//  - pass1: 16 LDG.128 -> sumsq via 5 shuffles (no barriers)
//  - pass2: re-read row (L1-hot) and FMA inv*x into a PER-WARP SMEM
//    accumulator region (8 KB/warp) -> regs ~40, 6 CTAs/SM
//  - block = 4 warps x 2 rows = 8 rows; grid 1024 = 8 blocks/batch

#define BB   128
#define NN   64
#define DD   2048
#define NF4  (DD / 4)      // 512 f4 columns
#define NT   128           // 4 warps
#define NW   4
#define CPB  8             // CTAs per batch
#define GRID (BB * CPB)    // 1024

__device__ float4       g_s[BB][CPB][NF4];  // per-(batch,eighth) col sums
__device__ float        g_diagp[GRID];
__device__ double       g_part[BB];
__device__ unsigned int g_pair[BB];         // monotonic (never reset)
__device__ unsigned int g_done;             // monotonic (never reset)

__global__ __launch_bounds__(NT, 8) void fused_loss(const float* __restrict__ x,
                                                    float* __restrict__ out) {
    __shared__ float4 sacc[NW][NF4];   // 32 KB: per-warp column accumulators
    __shared__ float  sdg[NW];
    __shared__ float  w1[NW];
    __shared__ bool   s_8th, s_last;
    __shared__ double sdd[NT];

    const int bid  = blockIdx.x;
    const int b    = bid >> 3;         // batch
    const int e    = bid & 7;          // eighth (8 rows)
    const int t    = threadIdx.x;
    const int warp = t >> 5;
    const int lane = t & 31;
    const float4* base4 = reinterpret_cast<const float4*>(x + (size_t)b * NN * DD);

    // zero this warp's accumulator region (warp-private, no barrier needed)
    #pragma unroll
    for (int j = 0; j < 16; j++)
        sacc[warp][lane + 32 * j] = make_float4(0.f, 0.f, 0.f, 0.f);

    float diag = 0.f;

    // ---------------- main loop: 2 rows per warp, barrier-free --------------
    #pragma unroll 1
    for (int r = 0; r < 2; r++) {
        const int row = e * 8 + warp * 2 + r;
        const float4* p = base4 + (size_t)row * NF4 + lane;

        // pass 1: sum of squares (4 chunks of 4 independent LDG.128)
        float c0 = 0.f, c1 = 0.f, c2 = 0.f, c3 = 0.f;
        #pragma unroll
        for (int c = 0; c < 4; c++) {
            const float4 v0 = p[(4 * c + 0) * 32];
            const float4 v1v = p[(4 * c + 1) * 32];
            const float4 v2 = p[(4 * c + 2) * 32];
            const float4 v3 = p[(4 * c + 3) * 32];
            c0 += v0.x*v0.x + v0.y*v0.y + v0.z*v0.z + v0.w*v0.w;
            c1 += v1v.x*v1v.x + v1v.y*v1v.y + v1v.z*v1v.z + v1v.w*v1v.w;
            c2 += v2.x*v2.x + v2.y*v2.y + v2.z*v2.z + v2.w*v2.w;
            c3 += v3.x*v3.x + v3.y*v3.y + v3.z*v3.z + v3.w*v3.w;
        }
        float ss = (c0 + c1) + (c2 + c3);
        #pragma unroll
        for (int o = 16; o; o >>= 1) ss += __shfl_xor_sync(0xffffffffu, ss, o);

        // inv = 1/max(||row||,1e-12)
        const float inv = rsqrtf(fmaxf(ss, 1e-24f));
        if (lane == 0) diag += ss * inv * inv;

        // pass 2: re-read row (L1-hot) and accumulate into smem acc
        #pragma unroll
        for (int j = 0; j < 16; j++) {
            const float4 a = p[j * 32];
            float4 s = sacc[warp][lane + 32 * j];
            s.x = fmaf(inv, a.x, s.x);
            s.y = fmaf(inv, a.y, s.y);
            s.z = fmaf(inv, a.z, s.z);
            s.w = fmaf(inv, a.w, s.w);
            sacc[warp][lane + 32 * j] = s;
        }
    }
    if (lane == 0) sdg[warp] = diag;
    __syncthreads();

    // ---------------- combine 4 warp regions -> eighth partial --------------
    // 128 threads x 4 f4 columns each
    #pragma unroll
    for (int j = 0; j < 4; j++) {
        const int col = t + NT * j;
        float4 a = sacc[0][col];
        const float4 q1 = sacc[1][col];
        const float4 q2 = sacc[2][col];
        const float4 q3 = sacc[3][col];
        a.x += q1.x + q2.x + q3.x;
        a.y += q1.y + q2.y + q3.y;
        a.z += q1.z + q2.z + q3.z;
        a.w += q1.w + q2.w + q3.w;
        g_s[b][e][col] = a;
    }
    if (t == 0) g_diagp[bid] = sdg[0] + sdg[1] + sdg[2] + sdg[3];
    __threadfence();
    __syncthreads();

    // ---------------- 8th-arriving block of batch computes t1 ---------------
    if (t == 0) {
        unsigned int old = atomicAdd(&g_pair[b], 1u);
        s_8th = ((old & 7u) == 7u);
    }
    __syncthreads();
    if (!s_8th) return;
    __threadfence();

    float v1 = 0.f;
    #pragma unroll
    for (int j = 0; j < 4; j++) {
        const int col = t + NT * j;
        float sx = 0.f, sy = 0.f, sz = 0.f, sw = 0.f;
        #pragma unroll
        for (int k = 0; k < CPB; k++) {
            const float4 q = g_s[b][k][col];
            sx += q.x; sy += q.y; sz += q.z; sw += q.w;
        }
        v1 += sx*sx + sy*sy + sz*sz + sw*sw;
    }
    #pragma unroll
    for (int o = 16; o; o >>= 1) v1 += __shfl_xor_sync(0xffffffffu, v1, o);
    if (lane == 0) w1[warp] = v1;
    __syncthreads();

    if (t == 0) {
        const float t1 = (w1[0] + w1[1]) + (w1[2] + w1[3]);
        double t2 = 0.0;
        #pragma unroll
        for (int k = 0; k < CPB; k++) t2 += (double)g_diagp[CPB * b + k];
        g_part[b] = (double)t1 - t2;
        __threadfence();
        unsigned int old = atomicAdd(&g_done, 1u);
        s_last = ((old & (unsigned int)(BB - 1)) == (unsigned int)(BB - 1));
    }
    __syncthreads();
    if (!s_last) return;

    // ---------------- finisher: combine 128 per-batch doubles ---------------
    __threadfence();
    sdd[t] = g_part[t];              // NT == BB == 128
    __syncthreads();
    #pragma unroll
    for (int o = NT / 2; o; o >>= 1) {
        if (t < o) sdd[t] += sdd[t + o];
        __syncthreads();
    }
    if (t == 0) out[0] = (float)(sdd[0] / (double)BB);
}

extern "C" void kernel_launch(void* const* d_in, const int* in_sizes, int n_in,
                              void* d_out, int out_size) {
    (void)in_sizes; (void)n_in; (void)out_size;
    const float* x = (const float*)d_in[0];
    float* out = (float*)d_out;
    fused_loss<<<GRID, NT>>>(x, out);
}

// round 14
// speedup vs baseline: 4.5845x; 4.5845x over previous
#include <cuda_runtime.h>

// inputs (128, 64, 64, 32) fp32 => B=128, N=64 rows/batch, D=2048.
// loss = mean_b( || sum_n att[b,n,:] ||^2 - sum_n <att_n,att_n> ),
// att = x / max(||x||,1e-12) row-wise.
//
// Subtile-interleaved single-CTA-per-batch design (grid 128 x 1024 thr,
// one CTA per SM -> full L1 available):
//   per 16-row subtile (128 KB, fits L1):
//     phase A: 2 warps/row stream the subtile from DRAM (populates L1),
//              row sumsq -> inv in smem            [1 barrier]
//     phase B: 2 threads/column re-read the subtile (L1 HITS, ~39cyc)
//              and FMA inv*x into register col accumulators [1 barrier]
// L2 sees the data once (64 MiB total vs R7's 128 MiB).

#define BB   128
#define NN   64
#define DD   2048
#define NF4  (DD / 4)      // 512 f4 columns
#define NT   1024
#define ST   4             // subtiles per batch
#define SR   16            // rows per subtile

__device__ double       g_part[BB];
__device__ unsigned int g_done;      // monotonic (never reset)

__global__ __launch_bounds__(NT) void fused_loss(const float* __restrict__ x,
                                                 float* __restrict__ out) {
    __shared__ float  wsA[SR][2];    // per-row half-sumsq partials
    __shared__ float  s_inv[SR];     // per-row inverse norms (this subtile)
    __shared__ float4 sbuf[NF4];     // half-combine of column accumulators
    __shared__ float  w1[NT / 32], w2[NT / 32];
    __shared__ bool   s_last;
    __shared__ double sdd[BB];

    const int b    = blockIdx.x;
    const int t    = threadIdx.x;
    const int warp = t >> 5;
    const int lane = t & 31;
    const float4* base4 = reinterpret_cast<const float4*>(x + (size_t)b * NN * DD);

    // phase-A role: warp pair (rA, hh) covers row rA's half hh (256 f4)
    const int rA = warp >> 1;
    const int hh = warp & 1;
    // phase-B role: thread owns column colB; half hB covers 8 rows/subtile
    const int colB = t & (NF4 - 1);
    const int hB   = t >> 9;

    float4 acc  = make_float4(0.f, 0.f, 0.f, 0.f);
    float  diag = 0.f;               // accumulated only by threads t<16

    #pragma unroll 1
    for (int s = 0; s < ST; s++) {
        // ---------- phase A: stream subtile, compute row norms ----------
        {
            const float4* p = base4 + (size_t)(s * SR + rA) * NF4 + hh * 256 + lane;
            float4 v[8];
            #pragma unroll
            for (int j = 0; j < 8; j++) v[j] = p[j * 32];
            float c0 = 0.f, c1 = 0.f, c2 = 0.f, c3 = 0.f;
            #pragma unroll
            for (int j = 0; j < 8; j += 4) {
                c0 += v[j+0].x*v[j+0].x + v[j+0].y*v[j+0].y + v[j+0].z*v[j+0].z + v[j+0].w*v[j+0].w;
                c1 += v[j+1].x*v[j+1].x + v[j+1].y*v[j+1].y + v[j+1].z*v[j+1].z + v[j+1].w*v[j+1].w;
                c2 += v[j+2].x*v[j+2].x + v[j+2].y*v[j+2].y + v[j+2].z*v[j+2].z + v[j+2].w*v[j+2].w;
                c3 += v[j+3].x*v[j+3].x + v[j+3].y*v[j+3].y + v[j+3].z*v[j+3].z + v[j+3].w*v[j+3].w;
            }
            float ss = (c0 + c1) + (c2 + c3);
            #pragma unroll
            for (int o = 16; o; o >>= 1) ss += __shfl_xor_sync(0xffffffffu, ss, o);
            if (lane == 0) wsA[rA][hh] = ss;
        }
        __syncthreads();

        if (t < SR) {
            const float rs  = wsA[t][0] + wsA[t][1];
            const float inv = rsqrtf(fmaxf(rs, 1e-24f));   // 1/max(||row||,1e-12)
            s_inv[t] = inv;
            diag += rs * inv * inv;
        }
        __syncthreads();

        // ---------- phase B: L1-hot re-read, weighted column accumulate ----
        {
            const float4* q = base4 + (size_t)(s * SR + hB * 8) * NF4 + colB;
            #pragma unroll
            for (int n = 0; n < 8; n++) {
                const float  w = s_inv[hB * 8 + n];
                const float4 a = q[n * NF4];
                acc.x = fmaf(w, a.x, acc.x);
                acc.y = fmaf(w, a.y, acc.y);
                acc.z = fmaf(w, a.z, acc.z);
                acc.w = fmaf(w, a.w, acc.w);
            }
        }
        // no barrier needed here: next phase A's wsA writes happen after
        // this thread's B; inv(s+1) is gated by bar1(s+1) which every
        // thread reaches only after finishing B(s).
    }

    // ---------------- combine the two row-halves per column -----------------
    if (hB == 1) sbuf[colB] = acc;
    __syncthreads();

    float v1 = 0.f;
    if (hB == 0) {
        const float4 q = sbuf[colB];
        const float sx = acc.x + q.x, sy = acc.y + q.y;
        const float sz = acc.z + q.z, sw = acc.w + q.w;
        v1 = sx * sx + sy * sy + sz * sz + sw * sw;
    }
    float v2 = diag;   // nonzero only on t<16 (warp 0)

    #pragma unroll
    for (int o = 16; o; o >>= 1) {
        v1 += __shfl_xor_sync(0xffffffffu, v1, o);
        v2 += __shfl_xor_sync(0xffffffffu, v2, o);
    }
    if (lane == 0) { w1[warp] = v1; w2[warp] = v2; }
    __syncthreads();

    __shared__ bool dummy_pad;  (void)dummy_pad;
    if (t == 0) {
        float t1 = 0.f, t2 = 0.f;
        #pragma unroll
        for (int i = 0; i < NT / 32; i++) { t1 += w1[i]; t2 += w2[i]; }
        g_part[b] = (double)t1 - (double)t2;
        __threadfence();
        unsigned int old = atomicAdd(&g_done, 1u);
        s_last = ((old & (unsigned int)(BB - 1)) == (unsigned int)(BB - 1));
    }
    __syncthreads();
    if (!s_last) return;

    // ---------------- finisher: combine 128 per-batch doubles ---------------
    __threadfence();
    if (t < BB) sdd[t] = g_part[t];
    __syncthreads();
    #pragma unroll
    for (int o = BB / 2; o; o >>= 1) {
        if (t < o) sdd[t] += sdd[t + o];
        __syncthreads();
    }
    if (t == 0) out[0] = (float)(sdd[0] / (double)BB);
}

extern "C" void kernel_launch(void* const* d_in, const int* in_sizes, int n_in,
                              void* d_out, int out_size) {
    (void)in_sizes; (void)n_in; (void)out_size;
    const float* x = (const float*)d_in[0];
    float* out = (float*)d_out;
    fused_loss<<<BB, NT>>>(x, out);
}

// round 15
// speedup vs baseline: 4.7743x; 1.0414x over previous
#include <cuda_runtime.h>

// inputs (128, 64, 64, 32) fp32 => B=128, N=64 rows/batch, D=2048.
// loss = mean_b( || sum_n att[b,n,:] ||^2 - sum_n <att_n,att_n> ),
// att = x / max(||x||,1e-12) row-wise.
//
// Subtile-interleaved single-CTA-per-batch design (grid 128 x 1024 thr),
// SOFTWARE-PIPELINED: subtile s+1's 8 LDG.128/thread are issued before the
// phase-A barrier, so the DRAM fetch of s+1 overlaps reduce+phase-B of s.
//   per 16-row subtile (128 KB):
//     phase A: 2 warps/row consume prefetched regs -> row sumsq -> inv
//     phase B: 2 threads/column re-read the subtile (L1/L2-hot) and
//              FMA inv*x into register column accumulators

#define BB   128
#define NN   64
#define DD   2048
#define NF4  (DD / 4)      // 512 f4 columns
#define NT   1024
#define ST   4             // subtiles per batch
#define SR   16            // rows per subtile

__device__ double       g_part[BB];
__device__ unsigned int g_done;      // monotonic (never reset)

__global__ __launch_bounds__(NT) void fused_loss(const float* __restrict__ x,
                                                 float* __restrict__ out) {
    __shared__ float  wsA[SR][2];    // per-row half-sumsq partials
    __shared__ float  s_inv[SR];     // per-row inverse norms (this subtile)
    __shared__ float4 sbuf[NF4];     // half-combine of column accumulators
    __shared__ float  w1[NT / 32], w2[NT / 32];
    __shared__ bool   s_last;
    __shared__ double sdd[BB];

    const int b    = blockIdx.x;
    const int t    = threadIdx.x;
    const int warp = t >> 5;
    const int lane = t & 31;
    const float4* base4 = reinterpret_cast<const float4*>(x + (size_t)b * NN * DD);

    // phase-A role: warp pair (rA, hh) covers row rA's half hh (256 f4)
    const int rA = warp >> 1;
    const int hh = warp & 1;
    // phase-B role: thread owns column colB; half hB covers 8 rows/subtile
    const int colB = t & (NF4 - 1);
    const int hB   = t >> 9;

    float4 acc  = make_float4(0.f, 0.f, 0.f, 0.f);
    float  diag = 0.f;               // accumulated only by threads t<16

    // prefetch subtile 0 (phase-A view)
    float4 v[8];
    {
        const float4* p = base4 + (size_t)rA * NF4 + hh * 256 + lane;
        #pragma unroll
        for (int j = 0; j < 8; j++) v[j] = p[j * 32];
    }

    #pragma unroll 1
    for (int s = 0; s < ST; s++) {
        // ---------- phase A: consume prefetched regs, compute row norms ----
        float c0 = 0.f, c1 = 0.f, c2 = 0.f, c3 = 0.f;
        #pragma unroll
        for (int j = 0; j < 8; j += 4) {
            c0 += v[j+0].x*v[j+0].x + v[j+0].y*v[j+0].y + v[j+0].z*v[j+0].z + v[j+0].w*v[j+0].w;
            c1 += v[j+1].x*v[j+1].x + v[j+1].y*v[j+1].y + v[j+1].z*v[j+1].z + v[j+1].w*v[j+1].w;
            c2 += v[j+2].x*v[j+2].x + v[j+2].y*v[j+2].y + v[j+2].z*v[j+2].z + v[j+2].w*v[j+2].w;
            c3 += v[j+3].x*v[j+3].x + v[j+3].y*v[j+3].y + v[j+3].z*v[j+3].z + v[j+3].w*v[j+3].w;
        }
        float ss = (c0 + c1) + (c2 + c3);
        #pragma unroll
        for (int o = 16; o; o >>= 1) ss += __shfl_xor_sync(0xffffffffu, ss, o);
        if (lane == 0) wsA[rA][hh] = ss;

        // issue subtile s+1's loads BEFORE the barrier: in flight during
        // reduce + phase B of subtile s (continuous DRAM stream)
        if (s < ST - 1) {
            const float4* p = base4 + (size_t)((s + 1) * SR + rA) * NF4 + hh * 256 + lane;
            #pragma unroll
            for (int j = 0; j < 8; j++) v[j] = p[j * 32];
        }
        __syncthreads();

        if (t < SR) {
            const float rs  = wsA[t][0] + wsA[t][1];
            const float inv = rsqrtf(fmaxf(rs, 1e-24f));   // 1/max(||row||,1e-12)
            s_inv[t] = inv;
            diag += rs * inv * inv;
        }
        __syncthreads();

        // ---------- phase B: cache-hot re-read, weighted column accumulate -
        {
            const float4* q = base4 + (size_t)(s * SR + hB * 8) * NF4 + colB;
            #pragma unroll
            for (int n = 0; n < 8; n++) {
                const float  w = s_inv[hB * 8 + n];
                const float4 a = q[n * NF4];
                acc.x = fmaf(w, a.x, acc.x);
                acc.y = fmaf(w, a.y, acc.y);
                acc.z = fmaf(w, a.z, acc.z);
                acc.w = fmaf(w, a.w, acc.w);
            }
        }
        // no barrier needed: inv(s+1) is gated by the next phase-A barrier,
        // which every thread reaches only after finishing B(s).
    }

    // ---------------- combine the two row-halves per column -----------------
    if (hB == 1) sbuf[colB] = acc;
    __syncthreads();

    float v1 = 0.f;
    if (hB == 0) {
        const float4 q = sbuf[colB];
        const float sx = acc.x + q.x, sy = acc.y + q.y;
        const float sz = acc.z + q.z, sw = acc.w + q.w;
        v1 = sx * sx + sy * sy + sz * sz + sw * sw;
    }
    float v2 = diag;   // nonzero only on t<16 (warp 0)

    #pragma unroll
    for (int o = 16; o; o >>= 1) {
        v1 += __shfl_xor_sync(0xffffffffu, v1, o);
        v2 += __shfl_xor_sync(0xffffffffu, v2, o);
    }
    if (lane == 0) { w1[warp] = v1; w2[warp] = v2; }
    __syncthreads();

    if (t == 0) {
        float t1 = 0.f, t2 = 0.f;
        #pragma unroll
        for (int i = 0; i < NT / 32; i++) { t1 += w1[i]; t2 += w2[i]; }
        g_part[b] = (double)t1 - (double)t2;
        __threadfence();
        unsigned int old = atomicAdd(&g_done, 1u);
        s_last = ((old & (unsigned int)(BB - 1)) == (unsigned int)(BB - 1));
    }
    __syncthreads();
    if (!s_last) return;

    // ---------------- finisher: combine 128 per-batch doubles ---------------
    __threadfence();
    if (t < BB) sdd[t] = g_part[t];
    __syncthreads();
    #pragma unroll
    for (int o = BB / 2; o; o >>= 1) {
        if (t < o) sdd[t] += sdd[t + o];
        __syncthreads();
    }
    if (t == 0) out[0] = (float)(sdd[0] / (double)BB);
}

extern "C" void kernel_launch(void* const* d_in, const int* in_sizes, int n_in,
                              void* d_out, int out_size) {
    (void)in_sizes; (void)n_in; (void)out_size;
    const float* x = (const float*)d_in[0];
    float* out = (float*)d_out;
    fused_loss<<<BB, NT>>>(x, out);
}